// round 4
// baseline (speedup 1.0000x reference)
#include <cuda_runtime.h>
#include <cuda_bf16.h>
#include <cstdint>

// ---------------- problem constants ----------------
#define Bc 8
#define Tc 16
#define Nn 1024
#define FIN 32
#define FOUT 64
#define Kc 3
#define CC 512            // T*F_in columns of the big GEMM

// ---------------- scratch (no cudaMalloc allowed) ----------------
__device__ __nv_bfloat16 g_xh[(size_t)Bc * CC * Nn];   // x transposed [b][c][j], hi bf16 (8 MB)
__device__ __nv_bfloat16 g_xl[(size_t)Bc * CC * Nn];   // lo bf16                        (8 MB)
__device__ float g_rhs[(size_t)Bc * Kc * Nn * CC];     // [b][k][i][c]                   (50 MB)

// ---------------- helpers ----------------
__device__ __forceinline__ uint32_t smem_u32(const void* p) {
    uint32_t a;
    asm("{ .reg .u64 t; cvta.to.shared.u64 t, %1; cvt.u32.u64 %0, t; }" : "=r"(a) : "l"(p));
    return a;
}

__device__ __forceinline__ void split2(float a, float b, uint32_t& hi, uint32_t& lo) {
    __nv_bfloat16 ha = __float2bfloat16_rn(a);
    __nv_bfloat16 hb = __float2bfloat16_rn(b);
    __nv_bfloat16 la = __float2bfloat16_rn(a - __bfloat162float(ha));
    __nv_bfloat16 lb = __float2bfloat16_rn(b - __bfloat162float(hb));
    hi = (uint32_t)__bfloat16_as_ushort(ha) | ((uint32_t)__bfloat16_as_ushort(hb) << 16);
    lo = (uint32_t)__bfloat16_as_ushort(la) | ((uint32_t)__bfloat16_as_ushort(lb) << 16);
}

__device__ __forceinline__ void mma16816(float* d, const uint32_t* a, uint32_t b0, uint32_t b1) {
    asm volatile(
        "mma.sync.aligned.m16n8k16.row.col.f32.bf16.bf16.f32 "
        "{%0,%1,%2,%3}, {%4,%5,%6,%7}, {%8,%9}, {%0,%1,%2,%3};"
        : "+f"(d[0]), "+f"(d[1]), "+f"(d[2]), "+f"(d[3])
        : "r"(a[0]), "r"(a[1]), "r"(a[2]), "r"(a[3]), "r"(b0), "r"(b1));
}

#define LDMATRIX_X4(r, addr) \
    asm volatile("ldmatrix.sync.aligned.m8n8.x4.shared.b16 {%0,%1,%2,%3}, [%4];" \
        : "=r"((r)[0]), "=r"((r)[1]), "=r"((r)[2]), "=r"((r)[3]) : "r"(addr))

#define CP_ASYNC16(dst_u32, src_ptr) \
    asm volatile("cp.async.cg.shared.global [%0], [%1], 16;" :: "r"(dst_u32), "l"(src_ptr))
#define CP_ASYNC_COMMIT() asm volatile("cp.async.commit_group;" ::: "memory")
#define CP_ASYNC_WAIT0()  asm volatile("cp.async.wait_group 0;" ::: "memory")
#define CP_ASYNC_WAIT1()  asm volatile("cp.async.wait_group 1;" ::: "memory")

// ---------------------------------------------------------------------------
// Kernel 1: x [b,t,j,f] -> xT hi/lo bf16 [b, c=t*32+f, j]
// ---------------------------------------------------------------------------
__global__ __launch_bounds__(256)
void k_prep_x(const float* __restrict__ x) {
    __shared__ float tile[128][33];
    const int blk = blockIdx.x;            // 8 jchunks * 16 t * 8 b = 1024
    const int jc = blk & 7;
    const int t  = (blk >> 3) & 15;
    const int b  = blk >> 7;
    const int j0 = jc * 128;
    const int tid = threadIdx.x;

    const float* src = x + (((size_t)b * Tc + t) * Nn + j0) * FIN;
    #pragma unroll
    for (int e = 0; e < 4; e++) {
        int li = e * 256 + tid;            // 1024 float4 (128 j-rows x 8 f4)
        int row = li >> 3, q = li & 7;
        float4 v = ((const float4*)src)[li];
        tile[row][q * 4 + 0] = v.x;
        tile[row][q * 4 + 1] = v.y;
        tile[row][q * 4 + 2] = v.z;
        tile[row][q * 4 + 3] = v.w;
    }
    __syncthreads();

    #pragma unroll
    for (int e = 0; e < 8; e++) {
        int li = e * 256 + tid;            // 2048 bf16x2 (32 f x 64 j-pairs)
        int f = li >> 6, jp = li & 63;
        int jj = jp * 2;
        uint32_t hi, lo;
        split2(tile[jj][f], tile[jj + 1][f], hi, lo);
        size_t off = ((size_t)b * CC + t * FIN + f) * Nn + j0 + jj;
        *(uint32_t*)((char*)g_xh + off * 2) = hi;
        *(uint32_t*)((char*)g_xl + off * 2) = lo;
    }
}

// ---------------------------------------------------------------------------
// Kernel 2: mma.sync GEMM, fused A = cheb*sa, bf16 hi/lo split (3 terms)
// CTA: M=128 x N=256, BK=32, 3-stage cp.async ring, 256 threads,
// 8 warps grid 2(M) x 4(N), warp tile 64x64.
// ---------------------------------------------------------------------------
#define BKg 32
#define NSTG 32
#define PITCH 80
#define OFF_AH 0
#define OFF_AL 10240
#define OFF_BH 20480
#define OFF_BL 40960
#define STG_SZ 61440
#define GEMM_SMEM (3 * STG_SZ)     // 184320 B

struct ARegs { float4 c[4], s[4]; };

__device__ __forceinline__ void ldgA(ARegs& ar, const float* __restrict__ Ach,
                                     const float* __restrict__ Asa, int j0, int tid) {
    const int row = tid >> 1;
    const int cb  = (tid & 1) * 16;
    const float* pc = Ach + (size_t)row * Nn + j0 + cb;
    const float* ps = Asa + (size_t)row * Nn + j0 + cb;
    #pragma unroll
    for (int q = 0; q < 4; q++) {
        ar.c[q] = *(const float4*)(pc + q * 4);
        ar.s[q] = *(const float4*)(ps + q * 4);
    }
}

__device__ __forceinline__ void stsA(const ARegs& ar, char* sbase, int tid) {
    const int row = tid >> 1;
    const int cb  = (tid & 1) * 16;
    uint32_t H[8], L[8];
    #pragma unroll
    for (int q = 0; q < 4; q++) {
        split2(ar.c[q].x * ar.s[q].x, ar.c[q].y * ar.s[q].y, H[2 * q], L[2 * q]);
        split2(ar.c[q].z * ar.s[q].z, ar.c[q].w * ar.s[q].w, H[2 * q + 1], L[2 * q + 1]);
    }
    char* ph = sbase + OFF_AH + row * PITCH + cb * 2;
    char* pl = sbase + OFF_AL + row * PITCH + cb * 2;
    *(uint4*)(ph)      = make_uint4(H[0], H[1], H[2], H[3]);
    *(uint4*)(ph + 16) = make_uint4(H[4], H[5], H[6], H[7]);
    *(uint4*)(pl)      = make_uint4(L[0], L[1], L[2], L[3]);
    *(uint4*)(pl + 16) = make_uint4(L[4], L[5], L[6], L[7]);
}

__device__ __forceinline__ void cpB(uint32_t sstage, const __nv_bfloat16* __restrict__ Bh,
                                    const __nv_bfloat16* __restrict__ Bl, int j0, int tid) {
    #pragma unroll
    for (int e = 0; e < 4; e++) {
        int li = tid + e * 256;            // 1024: 256 rows x 4 chunks of 16B
        int n = li >> 2, q = li & 3;
        const char* srcH = (const char*)(Bh + (size_t)n * Nn + j0) + q * 16;
        const char* srcL = (const char*)(Bl + (size_t)n * Nn + j0) + q * 16;
        CP_ASYNC16(sstage + OFF_BH + n * PITCH + q * 16, srcH);
        CP_ASYNC16(sstage + OFF_BL + n * PITCH + q * 16, srcL);
    }
}

__global__ __launch_bounds__(256, 1)
void k_gemm_mma(const float* __restrict__ cheb, const float* __restrict__ sa) {
    extern __shared__ char smem[];
    const uint32_t sb = smem_u32(smem);
    const int tid = threadIdx.x;
    const int lane = tid & 31, wid = tid >> 5;
    const int wm = wid >> 2, wn = wid & 3;          // warp grid 2 x 4, tile 64x64

    const int tile_c = blockIdx.x * 256;
    const int tile_i = blockIdx.y * 128;
    const int bk = blockIdx.z;
    const int b = bk / 3, kdeg = bk % 3;

    const float* Ach = cheb + (size_t)kdeg * Nn * Nn + (size_t)tile_i * Nn;
    const float* Asa = sa   + (size_t)b    * Nn * Nn + (size_t)tile_i * Nn;
    const __nv_bfloat16* Bh = g_xh + ((size_t)b * CC + tile_c) * Nn;
    const __nv_bfloat16* Bl = g_xl + ((size_t)b * CC + tile_c) * Nn;

    float acc[4][8][4];
    #pragma unroll
    for (int m = 0; m < 4; m++)
        #pragma unroll
        for (int n = 0; n < 8; n++)
            #pragma unroll
            for (int r = 0; r < 4; r++) acc[m][n][r] = 0.f;

    // per-lane ldmatrix offsets
    const uint32_t a_lane = (lane & 15) * PITCH + (lane >> 4) * 16;
    const uint32_t b_lane = ((lane & 7) + ((lane >> 4) << 3)) * PITCH + (((lane >> 3) & 1) << 4);
    const uint32_t a_base = wm * 64 * PITCH;
    const uint32_t b_base = wn * 64 * PITCH;

    // ---- prologue ----
    ARegs ar;
    ldgA(ar, Ach, Asa, 0, tid);
    stsA(ar, smem, tid);
    cpB(sb, Bh, Bl, 0, tid);
    CP_ASYNC_COMMIT();
    ldgA(ar, Ach, Asa, BKg, tid);          // A(1) in regs
    cpB(sb + STG_SZ, Bh, Bl, BKg, tid);
    CP_ASYNC_COMMIT();

    #pragma unroll 1
    for (int s = 0; s < NSTG; s++) {
        const int buf = s % 3;
        const uint32_t sbs = sb + buf * STG_SZ;

        if (s + 1 < NSTG) CP_ASYNC_WAIT1(); else CP_ASYNC_WAIT0();
        __syncthreads();

        if (s + 1 < NSTG) stsA(ar, smem + ((s + 1) % 3) * STG_SZ, tid);
        if (s + 2 < NSTG) {
            ldgA(ar, Ach, Asa, (s + 2) * BKg, tid);
            cpB(sb + ((s + 2) % 3) * STG_SZ, Bh, Bl, (s + 2) * BKg, tid);
            CP_ASYNC_COMMIT();
        }

        // ---- MMA on stage s ----
        #pragma unroll
        for (int ks = 0; ks < 2; ks++) {
            uint32_t ah[4][4], bh[4][4], bl[4][4], al[4][4];
            #pragma unroll
            for (int mt = 0; mt < 4; mt++)
                LDMATRIX_X4(ah[mt], sbs + OFF_AH + a_base + mt * 16 * PITCH + ks * 32 + a_lane);
            #pragma unroll
            for (int ng = 0; ng < 4; ng++)
                LDMATRIX_X4(bh[ng], sbs + OFF_BH + b_base + ng * 16 * PITCH + ks * 32 + b_lane);
            #pragma unroll
            for (int mt = 0; mt < 4; mt++)
                #pragma unroll
                for (int ng = 0; ng < 4; ng++) {
                    mma16816(acc[mt][2 * ng],     ah[mt], bh[ng][0], bh[ng][1]);
                    mma16816(acc[mt][2 * ng + 1], ah[mt], bh[ng][2], bh[ng][3]);
                }
            #pragma unroll
            for (int ng = 0; ng < 4; ng++)
                LDMATRIX_X4(bl[ng], sbs + OFF_BL + b_base + ng * 16 * PITCH + ks * 32 + b_lane);
            #pragma unroll
            for (int mt = 0; mt < 4; mt++)
                #pragma unroll
                for (int ng = 0; ng < 4; ng++) {
                    mma16816(acc[mt][2 * ng],     ah[mt], bl[ng][0], bl[ng][1]);
                    mma16816(acc[mt][2 * ng + 1], ah[mt], bl[ng][2], bl[ng][3]);
                }
            #pragma unroll
            for (int mt = 0; mt < 4; mt++)
                LDMATRIX_X4(al[mt], sbs + OFF_AL + a_base + mt * 16 * PITCH + ks * 32 + a_lane);
            #pragma unroll
            for (int mt = 0; mt < 4; mt++)
                #pragma unroll
                for (int ng = 0; ng < 4; ng++) {
                    mma16816(acc[mt][2 * ng],     al[mt], bh[ng][0], bh[ng][1]);
                    mma16816(acc[mt][2 * ng + 1], al[mt], bh[ng][2], bh[ng][3]);
                }
        }
    }

    // ---- epilogue ----
    float* Cb = g_rhs + (size_t)bk * Nn * CC;
    #pragma unroll
    for (int mt = 0; mt < 4; mt++) {
        int r0 = tile_i + wm * 64 + mt * 16 + (lane >> 2);
        #pragma unroll
        for (int nn = 0; nn < 8; nn++) {
            int c0 = tile_c + wn * 64 + nn * 8 + (lane & 3) * 2;
            *(float2*)(Cb + (size_t)r0 * CC + c0)       = make_float2(acc[mt][nn][0], acc[mt][nn][1]);
            *(float2*)(Cb + (size_t)(r0 + 8) * CC + c0) = make_float2(acc[mt][nn][2], acc[mt][nn][3]);
        }
    }
}

// ---------------------------------------------------------------------------
// Kernel 3: out[b,t,i,o] = relu( sum_{k,f} rhs[b,k,i,t*32+f] * Theta[k,f,o] )
// Theta register-resident (2 o per lane x 48 m per pass); rhs via warp-uniform
// broadcast LDS. Block: 256 thr = 8 warps, 8 i-rows, all t, all o.
// ---------------------------------------------------------------------------
#define PROJ_SMEM (24576 + 49152)      // ThS[96][64] + rv[128][96]

__global__ __launch_bounds__(256)
void k_proj(const float* __restrict__ Theta, float* __restrict__ out) {
    extern __shared__ float ps[];
    float* ThS = ps;                   // [96][64]
    float* rv  = ps + 96 * 64;         // [(ii*16+t)][96]

    const int blk = blockIdx.x;        // 8 b * 128 i-groups
    const int b = blk >> 7;
    const int i0 = (blk & 127) * 8;
    const int tid = threadIdx.x;
    const int lane = tid & 31, wid = tid >> 5;

    #pragma unroll
    for (int e = 0; e < 6; e++) {      // 1536 float4
        int li = tid + e * 256;
        ((float4*)ThS)[li] = ((const float4*)Theta)[li];
    }
    #pragma unroll
    for (int e = 0; e < 12; e++) {     // 3072 float4
        int li = tid + e * 256;
        int k = li >> 10, ii = (li >> 7) & 7, q = li & 127;
        int t = q >> 3, f4 = q & 7;
        float4 v = *(const float4*)(g_rhs + ((size_t)(b * Kc + k) * Nn + i0 + ii) * CC + q * 4);
        *(float4*)&rv[(ii * 16 + t) * 96 + k * 32 + f4 * 4] = v;
    }
    __syncthreads();

    // warp wid owns ii = wid; chunks of 4 t at a time
    #pragma unroll 1
    for (int c = 0; c < 4; c++) {
        const float* rp = &rv[(wid * 16 + c * 4) * 96];
        float2 a0 = make_float2(0.f, 0.f), a1 = a0, a2 = a0, a3 = a0;
        #pragma unroll
        for (int pass = 0; pass < 2; pass++) {
            float2 th[48];
            #pragma unroll
            for (int m = 0; m < 48; m++)
                th[m] = *(const float2*)&ThS[(pass * 48 + m) * 64 + 2 * lane];
            #pragma unroll
            for (int m = 0; m < 48; m += 2) {
                float2 r0 = *(const float2*)&rp[0 * 96 + pass * 48 + m];
                float2 r1 = *(const float2*)&rp[1 * 96 + pass * 48 + m];
                float2 r2 = *(const float2*)&rp[2 * 96 + pass * 48 + m];
                float2 r3 = *(const float2*)&rp[3 * 96 + pass * 48 + m];
                a0.x = fmaf(r0.x, th[m].x, a0.x);     a0.y = fmaf(r0.x, th[m].y, a0.y);
                a1.x = fmaf(r1.x, th[m].x, a1.x);     a1.y = fmaf(r1.x, th[m].y, a1.y);
                a2.x = fmaf(r2.x, th[m].x, a2.x);     a2.y = fmaf(r2.x, th[m].y, a2.y);
                a3.x = fmaf(r3.x, th[m].x, a3.x);     a3.y = fmaf(r3.x, th[m].y, a3.y);
                a0.x = fmaf(r0.y, th[m + 1].x, a0.x); a0.y = fmaf(r0.y, th[m + 1].y, a0.y);
                a1.x = fmaf(r1.y, th[m + 1].x, a1.x); a1.y = fmaf(r1.y, th[m + 1].y, a1.y);
                a2.x = fmaf(r2.y, th[m + 1].x, a2.x); a2.y = fmaf(r2.y, th[m + 1].y, a2.y);
                a3.x = fmaf(r3.y, th[m + 1].x, a3.x); a3.y = fmaf(r3.y, th[m + 1].y, a3.y);
            }
        }
        // store 4 t's with relu
        float2 av[4] = {a0, a1, a2, a3};
        #pragma unroll
        for (int q = 0; q < 4; q++) {
            int t = c * 4 + q;
            float2 v = make_float2(fmaxf(av[q].x, 0.f), fmaxf(av[q].y, 0.f));
            *(float2*)(out + (((size_t)b * Tc + t) * Nn + i0 + wid) * FOUT + 2 * lane) = v;
        }
    }
}

// ---------------------------------------------------------------------------
extern "C" void kernel_launch(void* const* d_in, const int* in_sizes, int n_in,
                              void* d_out, int out_size) {
    const float* x     = (const float*)d_in[0];
    const float* sa    = (const float*)d_in[1];
    const float* cheb  = (const float*)d_in[2];
    const float* Theta = (const float*)d_in[3];
    float* out = (float*)d_out;

    cudaFuncSetAttribute(k_gemm_mma, cudaFuncAttributeMaxDynamicSharedMemorySize, GEMM_SMEM);
    cudaFuncSetAttribute(k_proj, cudaFuncAttributeMaxDynamicSharedMemorySize, PROJ_SMEM);

    // 1) transpose + bf16 hi/lo split of x -> g_xh/g_xl [b][c][j]
    k_prep_x<<<1024, 256>>>(x);

    // 2) 24 fused (cheb*sa) GEMMs on tensor cores (mma.sync) -> g_rhs
    dim3 grid(2, 8, Bc * Kc);     // (c tiles, i tiles, b*k)
    k_gemm_mma<<<grid, 256, GEMM_SMEM>>>(cheb, sa);

    // 3) projection + relu -> out
    k_proj<<<Bc * 128, 256, PROJ_SMEM>>>(Theta, out);
}

// round 5
// speedup vs baseline: 1.1137x; 1.1137x over previous
#include <cuda_runtime.h>
#include <cuda_fp16.h>
#include <cstdint>

// ---------------- problem constants ----------------
#define Bc 8
#define Tc 16
#define Nn 1024
#define FIN 32
#define FOUT 64
#define Kc 3
#define CC 512            // T*F_in columns of the big GEMM

// ---------------- scratch (no cudaMalloc allowed) ----------------
__device__ __half g_xh[(size_t)Bc * CC * Nn];          // x transposed [b][c][j], hi fp16 (8 MB)
__device__ __half g_xl[(size_t)Bc * CC * Nn];          // lo fp16                        (8 MB)
__device__ float g_rhs[(size_t)Bc * Kc * Nn * CC];     // [b][k][i][c]                   (50 MB)

// ---------------- helpers ----------------
__device__ __forceinline__ uint32_t smem_u32(const void* p) {
    uint32_t a;
    asm("{ .reg .u64 t; cvta.to.shared.u64 t, %1; cvt.u32.u64 %0, t; }" : "=r"(a) : "l"(p));
    return a;
}

// fp16 hi/lo split of two floats, packed as half2 words
__device__ __forceinline__ void split2h(float a, float b, uint32_t& hi, uint32_t& lo) {
    __half ha = __float2half_rn(a);
    __half hb = __float2half_rn(b);
    __half la = __float2half_rn(a - __half2float(ha));
    __half lb = __float2half_rn(b - __half2float(hb));
    hi = (uint32_t)__half_as_ushort(ha) | ((uint32_t)__half_as_ushort(hb) << 16);
    lo = (uint32_t)__half_as_ushort(la) | ((uint32_t)__half_as_ushort(lb) << 16);
}

// pack two floats to half2 word (round-to-nearest)
__device__ __forceinline__ uint32_t pack2h(float a, float b) {
    __half ha = __float2half_rn(a);
    __half hb = __float2half_rn(b);
    return (uint32_t)__half_as_ushort(ha) | ((uint32_t)__half_as_ushort(hb) << 16);
}

__device__ __forceinline__ void mma16816(float* d, const uint32_t* a, uint32_t b0, uint32_t b1) {
    asm volatile(
        "mma.sync.aligned.m16n8k16.row.col.f32.f16.f16.f32 "
        "{%0,%1,%2,%3}, {%4,%5,%6,%7}, {%8,%9}, {%0,%1,%2,%3};"
        : "+f"(d[0]), "+f"(d[1]), "+f"(d[2]), "+f"(d[3])
        : "r"(a[0]), "r"(a[1]), "r"(a[2]), "r"(a[3]), "r"(b0), "r"(b1));
}

#define LDMATRIX_X4(r, addr) \
    asm volatile("ldmatrix.sync.aligned.m8n8.x4.shared.b16 {%0,%1,%2,%3}, [%4];" \
        : "=r"((r)[0]), "=r"((r)[1]), "=r"((r)[2]), "=r"((r)[3]) : "r"(addr))

#define CP_ASYNC16(dst_u32, src_ptr) \
    asm volatile("cp.async.cg.shared.global [%0], [%1], 16;" :: "r"(dst_u32), "l"(src_ptr))
#define CP_ASYNC_COMMIT() asm volatile("cp.async.commit_group;" ::: "memory")
#define CP_ASYNC_WAIT0()  asm volatile("cp.async.wait_group 0;" ::: "memory")

// ---------------------------------------------------------------------------
// Kernel 1: x [b,t,j,f] -> xT hi/lo fp16 [b, c=t*32+f, j]
// ---------------------------------------------------------------------------
__global__ __launch_bounds__(256)
void k_prep_x(const float* __restrict__ x) {
    __shared__ float tile[128][33];
    const int blk = blockIdx.x;            // 8 jchunks * 16 t * 8 b = 1024
    const int jc = blk & 7;
    const int t  = (blk >> 3) & 15;
    const int b  = blk >> 7;
    const int j0 = jc * 128;
    const int tid = threadIdx.x;

    const float* src = x + (((size_t)b * Tc + t) * Nn + j0) * FIN;
    #pragma unroll
    for (int e = 0; e < 4; e++) {
        int li = e * 256 + tid;            // 1024 float4 (128 j-rows x 8 f4)
        int row = li >> 3, q = li & 7;
        float4 v = ((const float4*)src)[li];
        tile[row][q * 4 + 0] = v.x;
        tile[row][q * 4 + 1] = v.y;
        tile[row][q * 4 + 2] = v.z;
        tile[row][q * 4 + 3] = v.w;
    }
    __syncthreads();

    #pragma unroll
    for (int e = 0; e < 8; e++) {
        int li = e * 256 + tid;            // 2048 half2 (32 f x 64 j-pairs)
        int f = li >> 6, jp = li & 63;
        int jj = jp * 2;
        uint32_t hi, lo;
        split2h(tile[jj][f], tile[jj + 1][f], hi, lo);
        size_t off = ((size_t)b * CC + t * FIN + f) * Nn + j0 + jj;
        *(uint32_t*)((char*)g_xh + off * 2) = hi;
        *(uint32_t*)((char*)g_xl + off * 2) = lo;
    }
}

// ---------------------------------------------------------------------------
// Kernel 2: mma.sync GEMM, fused A = fp16(cheb*sa), B = fp16 hi/lo (2 terms)
// CTA: M=128 x N=256, BK=32, double-buffered, 512 threads,
// 16 warps grid 2(M) x 8(N), warp tile 64x32.
// ---------------------------------------------------------------------------
#define BKg 32
#define NSTG 32
#define PITCH 80
#define OFF_A  0
#define OFF_BH 10240
#define OFF_BL 30720
#define STG_SZ 51200
#define GEMM_SMEM (2 * STG_SZ)      // 102400 B

struct AStage { float4 c[2], s[2]; };

__device__ __forceinline__ void ldg_A(AStage& st, const float* __restrict__ Ach,
                                      const float* __restrict__ Asa, int j0, int tid) {
    #pragma unroll
    for (int e = 0; e < 2; e++) {
        int li = tid + e * 512;            // 1024 float4 = 128 rows x 8 quads
        int row = li >> 3, q = li & 7;
        size_t g = (size_t)row * Nn + j0 + q * 4;
        st.c[e] = *(const float4*)(Ach + g);
        st.s[e] = *(const float4*)(Asa + g);
    }
}

__device__ __forceinline__ void sts_A(const AStage& st, char* sbase, int tid) {
    #pragma unroll
    for (int e = 0; e < 2; e++) {
        int li = tid + e * 512;
        int row = li >> 3, q = li & 7;
        uint32_t w0 = pack2h(st.c[e].x * st.s[e].x, st.c[e].y * st.s[e].y);
        uint32_t w1 = pack2h(st.c[e].z * st.s[e].z, st.c[e].w * st.s[e].w);
        *(uint2*)(sbase + OFF_A + row * PITCH + q * 8) = make_uint2(w0, w1);
    }
}

__device__ __forceinline__ void cpasync_B(uint32_t sstage, const __half* __restrict__ Bh,
                                          const __half* __restrict__ Bl, int j0, int tid) {
    #pragma unroll
    for (int e = 0; e < 2; e++) {
        int li = tid + e * 512;            // 1024: 256 rows x 4 chunks of 16B (per half)
        int n = li >> 2, q = li & 3;
        const char* srcH = (const char*)(Bh + (size_t)n * Nn + j0) + q * 16;
        const char* srcL = (const char*)(Bl + (size_t)n * Nn + j0) + q * 16;
        CP_ASYNC16(sstage + OFF_BH + n * PITCH + q * 16, srcH);
        CP_ASYNC16(sstage + OFF_BL + n * PITCH + q * 16, srcL);
    }
}

__global__ __launch_bounds__(512, 1)
void k_gemm_mma(const float* __restrict__ cheb, const float* __restrict__ sa) {
    extern __shared__ char smem[];
    const uint32_t sb = smem_u32(smem);
    const int tid = threadIdx.x;
    const int lane = tid & 31, wid = tid >> 5;
    const int wm = wid >> 3, wn = wid & 7;          // warp grid 2 x 8, tile 64x32

    const int tile_c = blockIdx.x * 256;
    const int tile_i = blockIdx.y * 128;
    const int bk = blockIdx.z;
    const int b = bk / 3, kdeg = bk % 3;

    const float* Ach = cheb + (size_t)kdeg * Nn * Nn + (size_t)tile_i * Nn;
    const float* Asa = sa   + (size_t)b    * Nn * Nn + (size_t)tile_i * Nn;
    const __half* Bh = g_xh + ((size_t)b * CC + tile_c) * Nn;
    const __half* Bl = g_xl + ((size_t)b * CC + tile_c) * Nn;

    float acc[4][4][4];
    #pragma unroll
    for (int m = 0; m < 4; m++)
        #pragma unroll
        for (int n = 0; n < 4; n++)
            #pragma unroll
            for (int r = 0; r < 4; r++) acc[m][n][r] = 0.f;

    // prologue: stage 0
    AStage st;
    ldg_A(st, Ach, Asa, 0, tid);
    sts_A(st, smem, tid);
    cpasync_B(sb, Bh, Bl, 0, tid);
    CP_ASYNC_COMMIT();

    const uint32_t arow_off = (lane & 15) * PITCH + (lane >> 4) * 16 + wm * 64 * PITCH;
    const uint32_t brow = (wn * 32 + (lane >> 2)) * PITCH + (lane & 3) * 4;

    #pragma unroll 1
    for (int s = 0; s < NSTG; s++) {
        const int buf = s & 1;
        char* cur = smem + buf * STG_SZ;
        char* nxt = smem + (buf ^ 1) * STG_SZ;
        const uint32_t sb_cur = sb + buf * STG_SZ;
        const uint32_t sb_nxt = sb + (buf ^ 1) * STG_SZ;

        if (s + 1 < NSTG) ldg_A(st, Ach, Asa, (s + 1) * BKg, tid);

        CP_ASYNC_WAIT0();
        __syncthreads();

        if (s + 1 < NSTG) {
            cpasync_B(sb_nxt, Bh, Bl, (s + 1) * BKg, tid);
            CP_ASYNC_COMMIT();
        }

        // ---- MMA on current stage: 2 terms (A*Bh + A*Bl) ----
        #pragma unroll
        for (int ks = 0; ks < 2; ks++) {
            uint32_t af[4][4];
            #pragma unroll
            for (int mt = 0; mt < 4; mt++)
                LDMATRIX_X4(af[mt], sb_cur + OFF_A + arow_off + mt * 16 * PITCH + ks * 32);
            #pragma unroll
            for (int nt = 0; nt < 4; nt++) {
                uint32_t bo = brow + nt * 8 * PITCH + ks * 32;
                uint32_t b0h = *(const uint32_t*)(cur + OFF_BH + bo);
                uint32_t b1h = *(const uint32_t*)(cur + OFF_BH + bo + 16);
                uint32_t b0l = *(const uint32_t*)(cur + OFF_BL + bo);
                uint32_t b1l = *(const uint32_t*)(cur + OFF_BL + bo + 16);
                #pragma unroll
                for (int mt = 0; mt < 4; mt++) {
                    mma16816(acc[mt][nt], af[mt], b0h, b1h);   // A * Bhi
                    mma16816(acc[mt][nt], af[mt], b0l, b1l);   // A * Blo
                }
            }
        }

        if (s + 1 < NSTG) sts_A(st, nxt, tid);
    }

    // ---- epilogue ----
    float* Cb = g_rhs + (size_t)bk * Nn * CC;
    #pragma unroll
    for (int mt = 0; mt < 4; mt++) {
        int r0 = tile_i + wm * 64 + mt * 16 + (lane >> 2);
        #pragma unroll
        for (int nt = 0; nt < 4; nt++) {
            int c0 = tile_c + wn * 32 + nt * 8 + (lane & 3) * 2;
            *(float2*)(Cb + (size_t)r0 * CC + c0)       = make_float2(acc[mt][nt][0], acc[mt][nt][1]);
            *(float2*)(Cb + (size_t)(r0 + 8) * CC + c0) = make_float2(acc[mt][nt][2], acc[mt][nt][3]);
        }
    }
}

// ---------------------------------------------------------------------------
// Kernel 3: out[b,t,i,o] = relu( sum_{k,f} rhs[b,k,i,t*32+f] * Theta[k,f,o] )
// (unchanged from the 309us kernel)
// ---------------------------------------------------------------------------
__global__ __launch_bounds__(256)
void k_proj(const float* __restrict__ Theta, float* __restrict__ out) {
    __shared__ float Th[96][FOUT];
    __shared__ float rv[Tc][96];

    const int blk = blockIdx.x;        // b*1024 + i
    const int b = blk >> 10;
    const int i = blk & 1023;
    const int tid = threadIdx.x;

    #pragma unroll
    for (int idx = tid; idx < 96 * FOUT; idx += 256)
        ((float*)Th)[idx] = Theta[idx];

    #pragma unroll
    for (int k = 0; k < Kc; k++) {
        const float* src = g_rhs + ((size_t)(b * Kc + k) * Nn + i) * CC;
        #pragma unroll
        for (int idx = tid; idx < CC; idx += 256) {
            int t = idx >> 5, f = idx & 31;
            rv[t][k * FIN + f] = src[idx];
        }
    }
    __syncthreads();

    #pragma unroll
    for (int e = 0; e < 4; e++) {
        int oidx = tid + e * 256;
        int t = oidx >> 6;
        int o = oidx & 63;
        float s = 0.f;
        #pragma unroll
        for (int m = 0; m < 96; m++)
            s = fmaf(rv[t][m], Th[m][o], s);
        out[(((size_t)b * Tc + t) * Nn + i) * FOUT + o] = fmaxf(s, 0.f);
    }
}

// ---------------------------------------------------------------------------
extern "C" void kernel_launch(void* const* d_in, const int* in_sizes, int n_in,
                              void* d_out, int out_size) {
    const float* x     = (const float*)d_in[0];
    const float* sa    = (const float*)d_in[1];
    const float* cheb  = (const float*)d_in[2];
    const float* Theta = (const float*)d_in[3];
    float* out = (float*)d_out;

    cudaFuncSetAttribute(k_gemm_mma, cudaFuncAttributeMaxDynamicSharedMemorySize, GEMM_SMEM);

    // 1) transpose + fp16 hi/lo split of x -> g_xh/g_xl [b][c][j]
    k_prep_x<<<1024, 256>>>(x);

    // 2) 24 fused (cheb*sa) GEMMs on tensor cores (mma.sync, 2-term fp16) -> g_rhs
    dim3 grid(2, 8, Bc * Kc);     // (c tiles, i tiles, b*k)
    k_gemm_mma<<<grid, 512, GEMM_SMEM>>>(cheb, sa);

    // 3) projection + relu -> out
    k_proj<<<Bc * Nn, 256>>>(Theta, out);
}

// round 6
// speedup vs baseline: 1.1700x; 1.0506x over previous
#include <cuda_runtime.h>
#include <cuda_fp16.h>
#include <cstdint>

// ---------------- problem constants ----------------
#define Bc 8
#define Tc 16
#define Nn 1024
#define FIN 32
#define FOUT 64
#define Kc 3
#define CC 512
#define NN (1024 * 1024)

// ---------------- scratch (no cudaMalloc allowed) ----------------
__device__ __half g_att[(size_t)Bc * Kc * NN];         // fp16(cheb*sa) [bk][i][j]  (50 MB)
__device__ __half g_xh[(size_t)Bc * CC * Nn];          // x^T hi fp16 [b][c][j]      (8 MB)
__device__ __half g_xl[(size_t)Bc * CC * Nn];          // x^T lo fp16                (8 MB)
__device__ float g_rhs[(size_t)Bc * Kc * Nn * CC];     // [b][k][i][c]               (50 MB)

// ---------------- helpers ----------------
__device__ __forceinline__ uint32_t smem_u32(const void* p) {
    uint32_t a;
    asm("{ .reg .u64 t; cvta.to.shared.u64 t, %1; cvt.u32.u64 %0, t; }" : "=r"(a) : "l"(p));
    return a;
}

__device__ __forceinline__ void split2h(float a, float b, uint32_t& hi, uint32_t& lo) {
    __half ha = __float2half_rn(a);
    __half hb = __float2half_rn(b);
    __half la = __float2half_rn(a - __half2float(ha));
    __half lb = __float2half_rn(b - __half2float(hb));
    hi = (uint32_t)__half_as_ushort(ha) | ((uint32_t)__half_as_ushort(hb) << 16);
    lo = (uint32_t)__half_as_ushort(la) | ((uint32_t)__half_as_ushort(lb) << 16);
}

__device__ __forceinline__ uint32_t pack2h(float a, float b) {
    __half ha = __float2half_rn(a);
    __half hb = __float2half_rn(b);
    return (uint32_t)__half_as_ushort(ha) | ((uint32_t)__half_as_ushort(hb) << 16);
}

__device__ __forceinline__ void mma16816(float* d, const uint32_t* a, uint32_t b0, uint32_t b1) {
    asm volatile(
        "mma.sync.aligned.m16n8k16.row.col.f32.f16.f16.f32 "
        "{%0,%1,%2,%3}, {%4,%5,%6,%7}, {%8,%9}, {%0,%1,%2,%3};"
        : "+f"(d[0]), "+f"(d[1]), "+f"(d[2]), "+f"(d[3])
        : "r"(a[0]), "r"(a[1]), "r"(a[2]), "r"(a[3]), "r"(b0), "r"(b1));
}

#define LDMATRIX_X4(r, addr) \
    asm volatile("ldmatrix.sync.aligned.m8n8.x4.shared.b16 {%0,%1,%2,%3}, [%4];" \
        : "=r"((r)[0]), "=r"((r)[1]), "=r"((r)[2]), "=r"((r)[3]) : "r"(addr))

#define CP_ASYNC16(dst_u32, src_ptr) \
    asm volatile("cp.async.cg.shared.global [%0], [%1], 16;" :: "r"(dst_u32), "l"(src_ptr))
#define CP_ASYNC_COMMIT() asm volatile("cp.async.commit_group;" ::: "memory")
#define CP_ASYNC_WAIT0()  asm volatile("cp.async.wait_group 0;" ::: "memory")

// ---------------------------------------------------------------------------
// Kernel 0: att[bk][i][j] = fp16(cheb[k,i,j] * sa[b,i,j])
// ---------------------------------------------------------------------------
__global__ __launch_bounds__(256)
void k_prep_att(const float* __restrict__ cheb, const float* __restrict__ sa) {
    int idx = blockIdx.x * 256 + threadIdx.x;          // quad index, 6.29M total
    int bk  = idx >> 18;                               // 256K quads per bk
    int pos = (idx & 0x3FFFF) * 4;
    int b = bk / 3, k = bk % 3;
    float4 c = *(const float4*)(cheb + (size_t)k * NN + pos);
    float4 s = *(const float4*)(sa   + (size_t)b * NN + pos);
    uint2 w = make_uint2(pack2h(c.x * s.x, c.y * s.y), pack2h(c.z * s.z, c.w * s.w));
    *(uint2*)(g_att + (size_t)bk * NN + pos) = w;
}

// ---------------------------------------------------------------------------
// Kernel 1: x [b,t,j,f] -> xT hi/lo fp16 [b, c=t*32+f, j]
// ---------------------------------------------------------------------------
__global__ __launch_bounds__(256)
void k_prep_x(const float* __restrict__ x) {
    __shared__ float tile[128][33];
    const int blk = blockIdx.x;
    const int jc = blk & 7;
    const int t  = (blk >> 3) & 15;
    const int b  = blk >> 7;
    const int j0 = jc * 128;
    const int tid = threadIdx.x;

    const float* src = x + (((size_t)b * Tc + t) * Nn + j0) * FIN;
    #pragma unroll
    for (int e = 0; e < 4; e++) {
        int li = e * 256 + tid;
        int row = li >> 3, q = li & 7;
        float4 v = ((const float4*)src)[li];
        tile[row][q * 4 + 0] = v.x;
        tile[row][q * 4 + 1] = v.y;
        tile[row][q * 4 + 2] = v.z;
        tile[row][q * 4 + 3] = v.w;
    }
    __syncthreads();

    #pragma unroll
    for (int e = 0; e < 8; e++) {
        int li = e * 256 + tid;
        int f = li >> 6, jp = li & 63;
        int jj = jp * 2;
        uint32_t hi, lo;
        split2h(tile[jj][f], tile[jj + 1][f], hi, lo);
        size_t off = ((size_t)b * CC + t * FIN + f) * Nn + j0 + jj;
        *(uint32_t*)((char*)g_xh + off * 2) = hi;
        *(uint32_t*)((char*)g_xl + off * 2) = lo;
    }
}

// ---------------------------------------------------------------------------
// Kernel 2: GEMM rhs[bk,i,c] = sum_j att[bk,i,j] * (xh+xl)[b,c,j]
// CTA 128(M) x 256(N), BK=64, 16 stages, double-buffered, all cp.async.
// 512 threads, 16 warps 2(M) x 8(N), warp tile 64x32. fp16 2-term.
// ---------------------------------------------------------------------------
#define BKg 64
#define NSTG 16
#define PITCH 144                       // 64 fp16 = 128B + 16B pad
#define OFF_A  0
#define A_SZ   (128 * PITCH)            // 18432
#define OFF_BH A_SZ
#define B_SZ   (256 * PITCH)            // 36864
#define OFF_BL (OFF_BH + B_SZ)
#define STG_SZ (A_SZ + 2 * B_SZ)        // 92160
#define GEMM_SMEM (2 * STG_SZ)          // 184320

__device__ __forceinline__ void cp_stage(uint32_t sstage, const __half* __restrict__ Ap,
                                         const __half* __restrict__ Bh,
                                         const __half* __restrict__ Bl, int j0, int tid) {
    // A: 128 rows x 8 chunks of 16B = 1024 -> 2 per thread
    #pragma unroll
    for (int e = 0; e < 2; e++) {
        int li = tid + e * 512;
        int row = li >> 3, q = li & 7;
        CP_ASYNC16(sstage + OFF_A + row * PITCH + q * 16,
                   (const char*)(Ap + (size_t)row * Nn + j0) + q * 16);
    }
    // B halves: 256 rows x 8 chunks each = 2048 -> 4 per thread per half
    #pragma unroll
    for (int e = 0; e < 4; e++) {
        int li = tid + e * 512;
        int n = li >> 3, q = li & 7;
        CP_ASYNC16(sstage + OFF_BH + n * PITCH + q * 16,
                   (const char*)(Bh + (size_t)n * Nn + j0) + q * 16);
        CP_ASYNC16(sstage + OFF_BL + n * PITCH + q * 16,
                   (const char*)(Bl + (size_t)n * Nn + j0) + q * 16);
    }
}

__global__ __launch_bounds__(512, 1)
void k_gemm_mma(int dummy) {
    extern __shared__ char smem[];
    const uint32_t sb = smem_u32(smem);
    const int tid = threadIdx.x;
    const int lane = tid & 31, wid = tid >> 5;
    const int wm = wid >> 3, wn = wid & 7;          // 2 x 8, warp tile 64x32

    const int tile_c = blockIdx.x * 256;
    const int tile_i = blockIdx.y * 128;
    const int bk = blockIdx.z;
    const int b = bk / 3;

    const __half* Ap = g_att + (size_t)bk * NN + (size_t)tile_i * Nn;
    const __half* Bh = g_xh + ((size_t)b * CC + tile_c) * Nn;
    const __half* Bl = g_xl + ((size_t)b * CC + tile_c) * Nn;

    float acc[4][4][4];
    #pragma unroll
    for (int m = 0; m < 4; m++)
        #pragma unroll
        for (int n = 0; n < 4; n++)
            #pragma unroll
            for (int r = 0; r < 4; r++) acc[m][n][r] = 0.f;

    // ldmatrix lane addressing
    const uint32_t a_off = wm * 64 * PITCH + (lane & 15) * PITCH + (lane >> 4) * 16;
    const uint32_t b_off = (wn * 32 + (lane & 7) + ((lane >> 4) << 3)) * PITCH
                         + ((lane >> 3) & 1) * 16;

    // prologue
    cp_stage(sb, Ap, Bh, Bl, 0, tid);
    CP_ASYNC_COMMIT();

    #pragma unroll 1
    for (int s = 0; s < NSTG; s++) {
        const int buf = s & 1;
        const uint32_t sbs = sb + buf * STG_SZ;

        CP_ASYNC_WAIT0();
        __syncthreads();

        if (s + 1 < NSTG) {
            cp_stage(sb + (buf ^ 1) * STG_SZ, Ap, Bh, Bl, (s + 1) * BKg, tid);
            CP_ASYNC_COMMIT();
        }

        // ---- MMA: 4 k16-chunks, 2 terms ----
        #pragma unroll
        for (int ks = 0; ks < 4; ks++) {
            uint32_t af[4][4], bhf[2][4], blf[2][4];
            #pragma unroll
            for (int mt = 0; mt < 4; mt++)
                LDMATRIX_X4(af[mt], sbs + OFF_A + a_off + mt * 16 * PITCH + ks * 32);
            #pragma unroll
            for (int ng = 0; ng < 2; ng++) {
                LDMATRIX_X4(bhf[ng], sbs + OFF_BH + b_off + ng * 16 * PITCH + ks * 32);
                LDMATRIX_X4(blf[ng], sbs + OFF_BL + b_off + ng * 16 * PITCH + ks * 32);
            }
            #pragma unroll
            for (int mt = 0; mt < 4; mt++)
                #pragma unroll
                for (int ng = 0; ng < 2; ng++) {
                    mma16816(acc[mt][2 * ng],     af[mt], bhf[ng][0], bhf[ng][1]);
                    mma16816(acc[mt][2 * ng + 1], af[mt], bhf[ng][2], bhf[ng][3]);
                    mma16816(acc[mt][2 * ng],     af[mt], blf[ng][0], blf[ng][1]);
                    mma16816(acc[mt][2 * ng + 1], af[mt], blf[ng][2], blf[ng][3]);
                }
        }
    }

    // ---- epilogue ----
    float* Cb = g_rhs + (size_t)bk * Nn * CC;
    #pragma unroll
    for (int mt = 0; mt < 4; mt++) {
        int r0 = tile_i + wm * 64 + mt * 16 + (lane >> 2);
        #pragma unroll
        for (int nt = 0; nt < 4; nt++) {
            int c0 = tile_c + wn * 32 + nt * 8 + (lane & 3) * 2;
            *(float2*)(Cb + (size_t)r0 * CC + c0)       = make_float2(acc[mt][nt][0], acc[mt][nt][1]);
            *(float2*)(Cb + (size_t)(r0 + 8) * CC + c0) = make_float2(acc[mt][nt][2], acc[mt][nt][3]);
        }
    }
}

// ---------------------------------------------------------------------------
// Kernel 3: out[b,t,i,o] = relu( sum_{k,f} rhs[b,k,i,t*32+f] * Theta[k,f,o] )
// ---------------------------------------------------------------------------
__global__ __launch_bounds__(256)
void k_proj(const float* __restrict__ Theta, float* __restrict__ out) {
    __shared__ float Th[96][FOUT];
    __shared__ float rv[Tc][96];

    const int blk = blockIdx.x;
    const int b = blk >> 10;
    const int i = blk & 1023;
    const int tid = threadIdx.x;

    #pragma unroll
    for (int idx = tid; idx < 96 * FOUT; idx += 256)
        ((float*)Th)[idx] = Theta[idx];

    #pragma unroll
    for (int k = 0; k < Kc; k++) {
        const float* src = g_rhs + ((size_t)(b * Kc + k) * Nn + i) * CC;
        #pragma unroll
        for (int idx = tid; idx < CC; idx += 256) {
            int t = idx >> 5, f = idx & 31;
            rv[t][k * FIN + f] = src[idx];
        }
    }
    __syncthreads();

    #pragma unroll
    for (int e = 0; e < 4; e++) {
        int oidx = tid + e * 256;
        int t = oidx >> 6;
        int o = oidx & 63;
        float s = 0.f;
        #pragma unroll
        for (int m = 0; m < 96; m++)
            s = fmaf(rv[t][m], Th[m][o], s);
        out[(((size_t)b * Tc + t) * Nn + i) * FOUT + o] = fmaxf(s, 0.f);
    }
}

// ---------------------------------------------------------------------------
extern "C" void kernel_launch(void* const* d_in, const int* in_sizes, int n_in,
                              void* d_out, int out_size) {
    const float* x     = (const float*)d_in[0];
    const float* sa    = (const float*)d_in[1];
    const float* cheb  = (const float*)d_in[2];
    const float* Theta = (const float*)d_in[3];
    float* out = (float*)d_out;

    cudaFuncSetAttribute(k_gemm_mma, cudaFuncAttributeMaxDynamicSharedMemorySize, GEMM_SMEM);

    // 0) att = fp16(cheb * sa)
    k_prep_att<<<24 * (NN / 4) / 256, 256>>>(cheb, sa);
    // 1) transpose + fp16 hi/lo split of x
    k_prep_x<<<1024, 256>>>(x);
    // 2) 24 GEMMs on tensor cores (2-term fp16, all-cp.async operands)
    dim3 grid(2, 8, Bc * Kc);
    k_gemm_mma<<<grid, 512, GEMM_SMEM>>>(0);
    // 3) projection + relu
    k_proj<<<Bc * Nn, 256>>>(Theta, out);
}

// round 7
// speedup vs baseline: 1.7537x; 1.4989x over previous
#include <cuda_runtime.h>
#include <cuda_fp16.h>
#include <cstdint>

// ---------------- problem constants ----------------
#define Bc 8
#define Tc 16
#define Nn 1024
#define FIN 32
#define FOUT 64
#define Kc 3
#define CC 512
#define NN (1024 * 1024)

// ---------------- scratch (no cudaMalloc allowed) ----------------
__device__ __half g_att[(size_t)Bc * Kc * NN];         // fp16(cheb*sa) [bk][i][j]  (50 MB)
__device__ __half g_xh[(size_t)Bc * CC * Nn];          // x^T hi fp16 [b][c][j]      (8 MB)
__device__ __half g_xl[(size_t)Bc * CC * Nn];          // x^T lo fp16                (8 MB)
__device__ __half g_rhsh[(size_t)Bc * Kc * Nn * CC];   // fp16 rhs [bk][i][c]        (25 MB)
__device__ __half g_tht[FOUT * 96];                    // Theta^T fp16 [o][m]

// ---------------- helpers ----------------
__device__ __forceinline__ uint32_t smem_u32(const void* p) {
    uint32_t a;
    asm("{ .reg .u64 t; cvta.to.shared.u64 t, %1; cvt.u32.u64 %0, t; }" : "=r"(a) : "l"(p));
    return a;
}

__device__ __forceinline__ void split2h(float a, float b, uint32_t& hi, uint32_t& lo) {
    __half ha = __float2half_rn(a);
    __half hb = __float2half_rn(b);
    __half la = __float2half_rn(a - __half2float(ha));
    __half lb = __float2half_rn(b - __half2float(hb));
    hi = (uint32_t)__half_as_ushort(ha) | ((uint32_t)__half_as_ushort(hb) << 16);
    lo = (uint32_t)__half_as_ushort(la) | ((uint32_t)__half_as_ushort(lb) << 16);
}

__device__ __forceinline__ uint32_t pack2h(float a, float b) {
    __half ha = __float2half_rn(a);
    __half hb = __float2half_rn(b);
    return (uint32_t)__half_as_ushort(ha) | ((uint32_t)__half_as_ushort(hb) << 16);
}

__device__ __forceinline__ void mma16816(float* d, const uint32_t* a, uint32_t b0, uint32_t b1) {
    asm volatile(
        "mma.sync.aligned.m16n8k16.row.col.f32.f16.f16.f32 "
        "{%0,%1,%2,%3}, {%4,%5,%6,%7}, {%8,%9}, {%0,%1,%2,%3};"
        : "+f"(d[0]), "+f"(d[1]), "+f"(d[2]), "+f"(d[3])
        : "r"(a[0]), "r"(a[1]), "r"(a[2]), "r"(a[3]), "r"(b0), "r"(b1));
}

#define LDMATRIX_X4(r, addr) \
    asm volatile("ldmatrix.sync.aligned.m8n8.x4.shared.b16 {%0,%1,%2,%3}, [%4];" \
        : "=r"((r)[0]), "=r"((r)[1]), "=r"((r)[2]), "=r"((r)[3]) : "r"(addr))

#define CP_ASYNC16(dst_u32, src_ptr) \
    asm volatile("cp.async.cg.shared.global [%0], [%1], 16;" :: "r"(dst_u32), "l"(src_ptr))
#define CP_ASYNC_COMMIT() asm volatile("cp.async.commit_group;" ::: "memory")
#define CP_ASYNC_WAIT0()  asm volatile("cp.async.wait_group 0;" ::: "memory")

// ---------------------------------------------------------------------------
// Kernel 0a: att[bk][i][j] = fp16(cheb[k,i,j] * sa[b,i,j])
// ---------------------------------------------------------------------------
__global__ __launch_bounds__(256)
void k_prep_att(const float* __restrict__ cheb, const float* __restrict__ sa) {
    int idx = blockIdx.x * 256 + threadIdx.x;
    int bk  = idx >> 18;
    int pos = (idx & 0x3FFFF) * 4;
    int b = bk / 3, k = bk % 3;
    float4 c = *(const float4*)(cheb + (size_t)k * NN + pos);
    float4 s = *(const float4*)(sa   + (size_t)b * NN + pos);
    uint2 w = make_uint2(pack2h(c.x * s.x, c.y * s.y), pack2h(c.z * s.z, c.w * s.w));
    *(uint2*)(g_att + (size_t)bk * NN + pos) = w;
}

// ---------------------------------------------------------------------------
// Kernel 0b: ThT[o][m] = fp16(Theta[m][o])   (96x64 -> 64x96)
// ---------------------------------------------------------------------------
__global__ __launch_bounds__(256)
void k_prep_tht(const float* __restrict__ Theta) {
    int idx = blockIdx.x * 256 + threadIdx.x;   // 6144
    int m = idx / FOUT, o = idx % FOUT;
    g_tht[o * 96 + m] = __float2half_rn(Theta[idx]);
}

// ---------------------------------------------------------------------------
// Kernel 1: x [b,t,j,f] -> xT hi/lo fp16 [b, c=t*32+f, j]
// ---------------------------------------------------------------------------
__global__ __launch_bounds__(256)
void k_prep_x(const float* __restrict__ x) {
    __shared__ float tile[128][33];
    const int blk = blockIdx.x;
    const int jc = blk & 7;
    const int t  = (blk >> 3) & 15;
    const int b  = blk >> 7;
    const int j0 = jc * 128;
    const int tid = threadIdx.x;

    const float* src = x + (((size_t)b * Tc + t) * Nn + j0) * FIN;
    #pragma unroll
    for (int e = 0; e < 4; e++) {
        int li = e * 256 + tid;
        int row = li >> 3, q = li & 7;
        float4 v = ((const float4*)src)[li];
        tile[row][q * 4 + 0] = v.x;
        tile[row][q * 4 + 1] = v.y;
        tile[row][q * 4 + 2] = v.z;
        tile[row][q * 4 + 3] = v.w;
    }
    __syncthreads();

    #pragma unroll
    for (int e = 0; e < 8; e++) {
        int li = e * 256 + tid;
        int f = li >> 6, jp = li & 63;
        int jj = jp * 2;
        uint32_t hi, lo;
        split2h(tile[jj][f], tile[jj + 1][f], hi, lo);
        size_t off = ((size_t)b * CC + t * FIN + f) * Nn + j0 + jj;
        *(uint32_t*)((char*)g_xh + off * 2) = hi;
        *(uint32_t*)((char*)g_xl + off * 2) = lo;
    }
}

// ---------------------------------------------------------------------------
// Kernel 2: GEMM rhs[bk,i,c] = sum_j att[bk,i,j] * (xh+xl)[b,c,j]  -> fp16 out
// CTA 128(M) x 256(N), BK=64, 16 stages, double-buffered, all cp.async.
// ---------------------------------------------------------------------------
#define BKg 64
#define NSTG 16
#define PITCH 144
#define OFF_A  0
#define A_SZ   (128 * PITCH)
#define OFF_BH A_SZ
#define B_SZ   (256 * PITCH)
#define OFF_BL (OFF_BH + B_SZ)
#define STG_SZ (A_SZ + 2 * B_SZ)
#define GEMM_SMEM (2 * STG_SZ)          // 184320

__device__ __forceinline__ void cp_stage(uint32_t sstage, const __half* __restrict__ Ap,
                                         const __half* __restrict__ Bh,
                                         const __half* __restrict__ Bl, int j0, int tid) {
    #pragma unroll
    for (int e = 0; e < 2; e++) {
        int li = tid + e * 512;
        int row = li >> 3, q = li & 7;
        CP_ASYNC16(sstage + OFF_A + row * PITCH + q * 16,
                   (const char*)(Ap + (size_t)row * Nn + j0) + q * 16);
    }
    #pragma unroll
    for (int e = 0; e < 4; e++) {
        int li = tid + e * 512;
        int n = li >> 3, q = li & 7;
        CP_ASYNC16(sstage + OFF_BH + n * PITCH + q * 16,
                   (const char*)(Bh + (size_t)n * Nn + j0) + q * 16);
        CP_ASYNC16(sstage + OFF_BL + n * PITCH + q * 16,
                   (const char*)(Bl + (size_t)n * Nn + j0) + q * 16);
    }
}

__global__ __launch_bounds__(512, 1)
void k_gemm_mma(int dummy) {
    extern __shared__ char smem[];
    const uint32_t sb = smem_u32(smem);
    const int tid = threadIdx.x;
    const int lane = tid & 31, wid = tid >> 5;
    const int wm = wid >> 3, wn = wid & 7;

    const int tile_c = blockIdx.x * 256;
    const int tile_i = blockIdx.y * 128;
    const int bk = blockIdx.z;
    const int b = bk / 3;

    const __half* Ap = g_att + (size_t)bk * NN + (size_t)tile_i * Nn;
    const __half* Bh = g_xh + ((size_t)b * CC + tile_c) * Nn;
    const __half* Bl = g_xl + ((size_t)b * CC + tile_c) * Nn;

    float acc[4][4][4];
    #pragma unroll
    for (int m = 0; m < 4; m++)
        #pragma unroll
        for (int n = 0; n < 4; n++)
            #pragma unroll
            for (int r = 0; r < 4; r++) acc[m][n][r] = 0.f;

    const uint32_t a_off = wm * 64 * PITCH + (lane & 15) * PITCH + (lane >> 4) * 16;
    const uint32_t b_off = (wn * 32 + (lane & 7) + ((lane >> 4) << 3)) * PITCH
                         + ((lane >> 3) & 1) * 16;

    cp_stage(sb, Ap, Bh, Bl, 0, tid);
    CP_ASYNC_COMMIT();

    #pragma unroll 1
    for (int s = 0; s < NSTG; s++) {
        const int buf = s & 1;
        const uint32_t sbs = sb + buf * STG_SZ;

        CP_ASYNC_WAIT0();
        __syncthreads();

        if (s + 1 < NSTG) {
            cp_stage(sb + (buf ^ 1) * STG_SZ, Ap, Bh, Bl, (s + 1) * BKg, tid);
            CP_ASYNC_COMMIT();
        }

        #pragma unroll
        for (int ks = 0; ks < 4; ks++) {
            uint32_t af[4][4], bhf[2][4], blf[2][4];
            #pragma unroll
            for (int mt = 0; mt < 4; mt++)
                LDMATRIX_X4(af[mt], sbs + OFF_A + a_off + mt * 16 * PITCH + ks * 32);
            #pragma unroll
            for (int ng = 0; ng < 2; ng++) {
                LDMATRIX_X4(bhf[ng], sbs + OFF_BH + b_off + ng * 16 * PITCH + ks * 32);
                LDMATRIX_X4(blf[ng], sbs + OFF_BL + b_off + ng * 16 * PITCH + ks * 32);
            }
            #pragma unroll
            for (int mt = 0; mt < 4; mt++)
                #pragma unroll
                for (int ng = 0; ng < 2; ng++) {
                    mma16816(acc[mt][2 * ng],     af[mt], bhf[ng][0], bhf[ng][1]);
                    mma16816(acc[mt][2 * ng + 1], af[mt], bhf[ng][2], bhf[ng][3]);
                    mma16816(acc[mt][2 * ng],     af[mt], blf[ng][0], blf[ng][1]);
                    mma16816(acc[mt][2 * ng + 1], af[mt], blf[ng][2], blf[ng][3]);
                }
        }
    }

    // ---- epilogue: fp16 store ----
    __half* Cb = g_rhsh + (size_t)bk * Nn * CC;
    #pragma unroll
    for (int mt = 0; mt < 4; mt++) {
        int r0 = tile_i + wm * 64 + mt * 16 + (lane >> 2);
        #pragma unroll
        for (int nt = 0; nt < 4; nt++) {
            int c0 = tile_c + wn * 32 + nt * 8 + (lane & 3) * 2;
            *(uint32_t*)(Cb + (size_t)r0 * CC + c0)       = pack2h(acc[mt][nt][0], acc[mt][nt][1]);
            *(uint32_t*)(Cb + (size_t)(r0 + 8) * CC + c0) = pack2h(acc[mt][nt][2], acc[mt][nt][3]);
        }
    }
}

// ---------------------------------------------------------------------------
// Kernel 3: tensor-core projection + ReLU
// CTA: 16 i x 16 t = 256 rows, K=96 (k*32+f), N=64 (o). 8 warps 4(M)x2(N).
// ---------------------------------------------------------------------------
#define P_PITCH 208                     // 96 halves = 192B + 16B pad
#define P_A_SZ  (256 * P_PITCH)         // 53248
#define P_B_OFF P_A_SZ
#define PROJ_SMEM (P_A_SZ + 64 * P_PITCH)   // 66560

__global__ __launch_bounds__(256, 2)
void k_proj_mma(float* __restrict__ out) {
    extern __shared__ char smem[];
    const uint32_t sb = smem_u32(smem);
    const int tid = threadIdx.x;
    const int lane = tid & 31, wid = tid >> 5;
    const int wm = wid >> 1, wn = wid & 1;     // 4(M) x 2(N)

    const int b  = blockIdx.y;
    const int i0 = blockIdx.x * 16;

    // ---- load A: rhs fp16, rows (il*16+t), cols m=k*32+f ----
    #pragma unroll
    for (int e = 0; e < 12; e++) {
        int li = tid + e * 256;                // 3072 chunks of 16B
        int k = li >> 10;
        int rem = li & 1023;
        int il = rem >> 6, q = rem & 63;       // q -> t = q>>2, fq = q&3
        int t = q >> 2, fq = q & 3;
        const char* src = (const char*)(g_rhsh + ((size_t)(b * 3 + k) * Nn + i0 + il) * CC) + q * 16;
        CP_ASYNC16(sb + (il * 16 + t) * P_PITCH + k * 64 + fq * 16, src);
    }
    // ---- load ThT: 64 rows x 12 chunks ----
    #pragma unroll
    for (int e = 0; e < 3; e++) {
        int li = tid + e * 256;                // 768
        int row = li / 12, q = li % 12;
        CP_ASYNC16(sb + P_B_OFF + row * P_PITCH + q * 16,
                   (const char*)(g_tht + row * 96) + q * 8 * 2);
    }
    CP_ASYNC_COMMIT();
    CP_ASYNC_WAIT0();
    __syncthreads();

    float acc[4][4][4];
    #pragma unroll
    for (int m = 0; m < 4; m++)
        #pragma unroll
        for (int n = 0; n < 4; n++)
            #pragma unroll
            for (int r = 0; r < 4; r++) acc[m][n][r] = 0.f;

    const uint32_t a_off = wm * 64 * P_PITCH + (lane & 15) * P_PITCH + (lane >> 4) * 16;
    const uint32_t b_off = P_B_OFF + (wn * 32 + (lane & 7) + ((lane >> 4) << 3)) * P_PITCH
                         + ((lane >> 3) & 1) * 16;

    #pragma unroll
    for (int ks = 0; ks < 6; ks++) {
        uint32_t af[4][4], bf[2][4];
        #pragma unroll
        for (int mt = 0; mt < 4; mt++)
            LDMATRIX_X4(af[mt], sb + a_off + mt * 16 * P_PITCH + ks * 32);
        #pragma unroll
        for (int ng = 0; ng < 2; ng++)
            LDMATRIX_X4(bf[ng], sb + b_off + ng * 16 * P_PITCH + ks * 32);
        #pragma unroll
        for (int mt = 0; mt < 4; mt++)
            #pragma unroll
            for (int ng = 0; ng < 2; ng++) {
                mma16816(acc[mt][2 * ng],     af[mt], bf[ng][0], bf[ng][1]);
                mma16816(acc[mt][2 * ng + 1], af[mt], bf[ng][2], bf[ng][3]);
            }
    }

    // ---- store with ReLU: row r = il*16 + t ----
    #pragma unroll
    for (int mt = 0; mt < 4; mt++) {
        int il = wm * 4 + mt;
        int t0 = lane >> 2;
        #pragma unroll
        for (int nt = 0; nt < 4; nt++) {
            int o = wn * 32 + nt * 8 + (lane & 3) * 2;
            float* p0 = out + (((size_t)b * Tc + t0)     * Nn + i0 + il) * FOUT + o;
            float* p1 = out + (((size_t)b * Tc + t0 + 8) * Nn + i0 + il) * FOUT + o;
            *(float2*)p0 = make_float2(fmaxf(acc[mt][nt][0], 0.f), fmaxf(acc[mt][nt][1], 0.f));
            *(float2*)p1 = make_float2(fmaxf(acc[mt][nt][2], 0.f), fmaxf(acc[mt][nt][3], 0.f));
        }
    }
}

// ---------------------------------------------------------------------------
extern "C" void kernel_launch(void* const* d_in, const int* in_sizes, int n_in,
                              void* d_out, int out_size) {
    const float* x     = (const float*)d_in[0];
    const float* sa    = (const float*)d_in[1];
    const float* cheb  = (const float*)d_in[2];
    const float* Theta = (const float*)d_in[3];
    float* out = (float*)d_out;

    cudaFuncSetAttribute(k_gemm_mma, cudaFuncAttributeMaxDynamicSharedMemorySize, GEMM_SMEM);
    cudaFuncSetAttribute(k_proj_mma, cudaFuncAttributeMaxDynamicSharedMemorySize, PROJ_SMEM);

    // 0) att = fp16(cheb * sa); ThT = fp16(Theta^T)
    k_prep_att<<<24 * (NN / 4) / 256, 256>>>(cheb, sa);
    k_prep_tht<<<24, 256>>>(Theta);
    // 1) transpose + fp16 hi/lo split of x
    k_prep_x<<<1024, 256>>>(x);
    // 2) 24 GEMMs on tensor cores -> fp16 rhs
    dim3 grid(2, 8, Bc * Kc);
    k_gemm_mma<<<grid, 512, GEMM_SMEM>>>(0);
    // 3) tensor-core projection + relu
    dim3 pgrid(64, Bc);
    k_proj_mma<<<pgrid, 256, PROJ_SMEM>>>(out);
}

// round 8
// speedup vs baseline: 2.6867x; 1.5320x over previous
#include <cuda_runtime.h>
#include <cuda_fp16.h>
#include <cstdint>

// ---------------- problem constants ----------------
#define Bc 8
#define Tc 16
#define Nn 1024
#define FIN 32
#define FOUT 64
#define Kc 3
#define CC 512
#define NN (1024 * 1024)

// ---------------- scratch (no cudaMalloc allowed) ----------------
__device__ __half g_att[(size_t)Bc * Kc * NN];         // fp16(cheb*sa) [bk][i][j]  (50 MB)
__device__ __half g_xh[(size_t)Bc * CC * Nn];          // x^T fp16 [b][c][j]         (8 MB)
__device__ __half g_rhsh[(size_t)Bc * Kc * Nn * CC];   // fp16 rhs [bk][i][c]        (25 MB)
__device__ __half g_tht[FOUT * 96];                    // Theta^T fp16 [o][m]

// ---------------- helpers ----------------
__device__ __forceinline__ uint32_t smem_u32(const void* p) {
    uint32_t a;
    asm("{ .reg .u64 t; cvta.to.shared.u64 t, %1; cvt.u32.u64 %0, t; }" : "=r"(a) : "l"(p));
    return a;
}

__device__ __forceinline__ uint32_t pack2h(float a, float b) {
    __half ha = __float2half_rn(a);
    __half hb = __float2half_rn(b);
    return (uint32_t)__half_as_ushort(ha) | ((uint32_t)__half_as_ushort(hb) << 16);
}

__device__ __forceinline__ void mma16816(float* d, const uint32_t* a, uint32_t b0, uint32_t b1) {
    asm volatile(
        "mma.sync.aligned.m16n8k16.row.col.f32.f16.f16.f32 "
        "{%0,%1,%2,%3}, {%4,%5,%6,%7}, {%8,%9}, {%0,%1,%2,%3};"
        : "+f"(d[0]), "+f"(d[1]), "+f"(d[2]), "+f"(d[3])
        : "r"(a[0]), "r"(a[1]), "r"(a[2]), "r"(a[3]), "r"(b0), "r"(b1));
}

#define LDMATRIX_X4(r, addr) \
    asm volatile("ldmatrix.sync.aligned.m8n8.x4.shared.b16 {%0,%1,%2,%3}, [%4];" \
        : "=r"((r)[0]), "=r"((r)[1]), "=r"((r)[2]), "=r"((r)[3]) : "r"(addr))

#define CP_ASYNC16(dst_u32, src_ptr) \
    asm volatile("cp.async.cg.shared.global [%0], [%1], 16;" :: "r"(dst_u32), "l"(src_ptr))
#define CP_ASYNC_COMMIT() asm volatile("cp.async.commit_group;" ::: "memory")
#define CP_ASYNC_WAIT0()  asm volatile("cp.async.wait_group 0;" ::: "memory")

// ---------------------------------------------------------------------------
// Kernel 0a: att[bk][i][j] = fp16(cheb[k,i,j] * sa[b,i,j])
// ---------------------------------------------------------------------------
__global__ __launch_bounds__(256)
void k_prep_att(const float* __restrict__ cheb, const float* __restrict__ sa) {
    int idx = blockIdx.x * 256 + threadIdx.x;
    int bk  = idx >> 18;
    int pos = (idx & 0x3FFFF) * 4;
    int b = bk / 3, k = bk % 3;
    float4 c = *(const float4*)(cheb + (size_t)k * NN + pos);
    float4 s = *(const float4*)(sa   + (size_t)b * NN + pos);
    uint2 w = make_uint2(pack2h(c.x * s.x, c.y * s.y), pack2h(c.z * s.z, c.w * s.w));
    *(uint2*)(g_att + (size_t)bk * NN + pos) = w;
}

// ---------------------------------------------------------------------------
// Kernel 0b: ThT[o][m] = fp16(Theta[m][o])
// ---------------------------------------------------------------------------
__global__ __launch_bounds__(256)
void k_prep_tht(const float* __restrict__ Theta) {
    int idx = blockIdx.x * 256 + threadIdx.x;   // 6144
    int m = idx / FOUT, o = idx % FOUT;
    g_tht[o * 96 + m] = __float2half_rn(Theta[idx]);
}

// ---------------------------------------------------------------------------
// Kernel 1: x [b,t,j,f] -> xT fp16 [b, c=t*32+f, j]
// ---------------------------------------------------------------------------
__global__ __launch_bounds__(256)
void k_prep_x(const float* __restrict__ x) {
    __shared__ float tile[128][33];
    const int blk = blockIdx.x;
    const int jc = blk & 7;
    const int t  = (blk >> 3) & 15;
    const int b  = blk >> 7;
    const int j0 = jc * 128;
    const int tid = threadIdx.x;

    const float* src = x + (((size_t)b * Tc + t) * Nn + j0) * FIN;
    #pragma unroll
    for (int e = 0; e < 4; e++) {
        int li = e * 256 + tid;
        int row = li >> 3, q = li & 7;
        float4 v = ((const float4*)src)[li];
        tile[row][q * 4 + 0] = v.x;
        tile[row][q * 4 + 1] = v.y;
        tile[row][q * 4 + 2] = v.z;
        tile[row][q * 4 + 3] = v.w;
    }
    __syncthreads();

    #pragma unroll
    for (int e = 0; e < 8; e++) {
        int li = e * 256 + tid;
        int f = li >> 6, jp = li & 63;
        int jj = jp * 2;
        uint32_t w = pack2h(tile[jj][f], tile[jj + 1][f]);
        size_t off = ((size_t)b * CC + t * FIN + f) * Nn + j0 + jj;
        *(uint32_t*)((char*)g_xh + off * 2) = w;
    }
}

// ---------------------------------------------------------------------------
// Kernel 2: GEMM rhs[bk,i,c] = sum_j att[bk,i,j] * x[b,c,j]   (1-term fp16)
// CTA 128(M) x 128(N), BK=64, double-buffered, 256 threads,
// 8 warps 2(M) x 4(N), warp tile 64x32. 2 CTAs/SM.
// ---------------------------------------------------------------------------
#define BKg 64
#define NSTG 16
#define PITCH 144                       // 64 fp16 = 128B + 16B pad
#define OFF_A  0
#define A_SZ   (128 * PITCH)            // 18432
#define OFF_B  A_SZ
#define B_SZ   (128 * PITCH)            // 18432
#define STG_SZ (A_SZ + B_SZ)            // 36864
#define GEMM_SMEM (2 * STG_SZ)          // 73728

__device__ __forceinline__ void cp_stage(uint32_t sstage, const __half* __restrict__ Ap,
                                         const __half* __restrict__ Bp, int j0, int tid) {
    // A: 128 rows x 8 chunks of 16B = 1024 -> 4 per thread
    #pragma unroll
    for (int e = 0; e < 4; e++) {
        int li = tid + e * 256;
        int row = li >> 3, q = li & 7;
        CP_ASYNC16(sstage + OFF_A + row * PITCH + q * 16,
                   (const char*)(Ap + (size_t)row * Nn + j0) + q * 16);
    }
    // B: 128 rows x 8 chunks of 16B = 1024 -> 4 per thread
    #pragma unroll
    for (int e = 0; e < 4; e++) {
        int li = tid + e * 256;
        int n = li >> 3, q = li & 7;
        CP_ASYNC16(sstage + OFF_B + n * PITCH + q * 16,
                   (const char*)(Bp + (size_t)n * Nn + j0) + q * 16);
    }
}

__global__ __launch_bounds__(256, 2)
void k_gemm_mma(int dummy) {
    extern __shared__ char smem[];
    const uint32_t sb = smem_u32(smem);
    const int tid = threadIdx.x;
    const int lane = tid & 31, wid = tid >> 5;
    const int wm = wid >> 2, wn = wid & 3;          // 2 x 4, warp tile 64x32

    const int tile_c = blockIdx.x * 128;
    const int tile_i = blockIdx.y * 128;
    const int bk = blockIdx.z;
    const int b = bk / 3;

    const __half* Ap = g_att + (size_t)bk * NN + (size_t)tile_i * Nn;
    const __half* Bp = g_xh + ((size_t)b * CC + tile_c) * Nn;

    float acc[4][4][4];
    #pragma unroll
    for (int m = 0; m < 4; m++)
        #pragma unroll
        for (int n = 0; n < 4; n++)
            #pragma unroll
            for (int r = 0; r < 4; r++) acc[m][n][r] = 0.f;

    const uint32_t a_off = wm * 64 * PITCH + (lane & 15) * PITCH + (lane >> 4) * 16;
    const uint32_t b_off = (wn * 32 + (lane & 7) + ((lane >> 4) << 3)) * PITCH
                         + ((lane >> 3) & 1) * 16;

    cp_stage(sb, Ap, Bp, 0, tid);
    CP_ASYNC_COMMIT();

    #pragma unroll 1
    for (int s = 0; s < NSTG; s++) {
        const int buf = s & 1;
        const uint32_t sbs = sb + buf * STG_SZ;

        CP_ASYNC_WAIT0();
        __syncthreads();

        if (s + 1 < NSTG) {
            cp_stage(sb + (buf ^ 1) * STG_SZ, Ap, Bp, (s + 1) * BKg, tid);
            CP_ASYNC_COMMIT();
        }

        // ---- MMA: 4 k16-chunks, 1 term ----
        #pragma unroll
        for (int ks = 0; ks < 4; ks++) {
            uint32_t af[4][4], bf[2][4];
            #pragma unroll
            for (int mt = 0; mt < 4; mt++)
                LDMATRIX_X4(af[mt], sbs + OFF_A + a_off + mt * 16 * PITCH + ks * 32);
            #pragma unroll
            for (int ng = 0; ng < 2; ng++)
                LDMATRIX_X4(bf[ng], sbs + OFF_B + b_off + ng * 16 * PITCH + ks * 32);
            #pragma unroll
            for (int mt = 0; mt < 4; mt++)
                #pragma unroll
                for (int ng = 0; ng < 2; ng++) {
                    mma16816(acc[mt][2 * ng],     af[mt], bf[ng][0], bf[ng][1]);
                    mma16816(acc[mt][2 * ng + 1], af[mt], bf[ng][2], bf[ng][3]);
                }
        }
    }

    // ---- epilogue: fp16 store ----
    __half* Cb = g_rhsh + (size_t)bk * Nn * CC;
    #pragma unroll
    for (int mt = 0; mt < 4; mt++) {
        int r0 = tile_i + wm * 64 + mt * 16 + (lane >> 2);
        #pragma unroll
        for (int nt = 0; nt < 4; nt++) {
            int c0 = tile_c + wn * 32 + nt * 8 + (lane & 3) * 2;
            *(uint32_t*)(Cb + (size_t)r0 * CC + c0)       = pack2h(acc[mt][nt][0], acc[mt][nt][1]);
            *(uint32_t*)(Cb + (size_t)(r0 + 8) * CC + c0) = pack2h(acc[mt][nt][2], acc[mt][nt][3]);
        }
    }
}

// ---------------------------------------------------------------------------
// Kernel 3: tensor-core projection + ReLU
// CTA: 16 i x 16 t = 256 rows, K=96, N=64. 8 warps 4(M)x2(N).
// ---------------------------------------------------------------------------
#define P_PITCH 208
#define P_A_SZ  (256 * P_PITCH)
#define P_B_OFF P_A_SZ
#define PROJ_SMEM (P_A_SZ + 64 * P_PITCH)   // 66560

__global__ __launch_bounds__(256, 2)
void k_proj_mma(float* __restrict__ out) {
    extern __shared__ char smem[];
    const uint32_t sb = smem_u32(smem);
    const int tid = threadIdx.x;
    const int lane = tid & 31, wid = tid >> 5;
    const int wm = wid >> 1, wn = wid & 1;

    const int b  = blockIdx.y;
    const int i0 = blockIdx.x * 16;

    #pragma unroll
    for (int e = 0; e < 12; e++) {
        int li = tid + e * 256;
        int k = li >> 10;
        int rem = li & 1023;
        int il = rem >> 6, q = rem & 63;
        int t = q >> 2, fq = q & 3;
        const char* src = (const char*)(g_rhsh + ((size_t)(b * 3 + k) * Nn + i0 + il) * CC) + q * 16;
        CP_ASYNC16(sb + (il * 16 + t) * P_PITCH + k * 64 + fq * 16, src);
    }
    #pragma unroll
    for (int e = 0; e < 3; e++) {
        int li = tid + e * 256;
        int row = li / 12, q = li % 12;
        CP_ASYNC16(sb + P_B_OFF + row * P_PITCH + q * 16,
                   (const char*)(g_tht + row * 96) + q * 16);
    }
    CP_ASYNC_COMMIT();
    CP_ASYNC_WAIT0();
    __syncthreads();

    float acc[4][4][4];
    #pragma unroll
    for (int m = 0; m < 4; m++)
        #pragma unroll
        for (int n = 0; n < 4; n++)
            #pragma unroll
            for (int r = 0; r < 4; r++) acc[m][n][r] = 0.f;

    const uint32_t a_off = wm * 64 * P_PITCH + (lane & 15) * P_PITCH + (lane >> 4) * 16;
    const uint32_t b_off = P_B_OFF + (wn * 32 + (lane & 7) + ((lane >> 4) << 3)) * P_PITCH
                         + ((lane >> 3) & 1) * 16;

    #pragma unroll
    for (int ks = 0; ks < 6; ks++) {
        uint32_t af[4][4], bf[2][4];
        #pragma unroll
        for (int mt = 0; mt < 4; mt++)
            LDMATRIX_X4(af[mt], sb + a_off + mt * 16 * P_PITCH + ks * 32);
        #pragma unroll
        for (int ng = 0; ng < 2; ng++)
            LDMATRIX_X4(bf[ng], sb + b_off + ng * 16 * P_PITCH + ks * 32);
        #pragma unroll
        for (int mt = 0; mt < 4; mt++)
            #pragma unroll
            for (int ng = 0; ng < 2; ng++) {
                mma16816(acc[mt][2 * ng],     af[mt], bf[ng][0], bf[ng][1]);
                mma16816(acc[mt][2 * ng + 1], af[mt], bf[ng][2], bf[ng][3]);
            }
    }

    #pragma unroll
    for (int mt = 0; mt < 4; mt++) {
        int il = wm * 4 + mt;
        int t0 = lane >> 2;
        #pragma unroll
        for (int nt = 0; nt < 4; nt++) {
            int o = wn * 32 + nt * 8 + (lane & 3) * 2;
            float* p0 = out + (((size_t)b * Tc + t0)     * Nn + i0 + il) * FOUT + o;
            float* p1 = out + (((size_t)b * Tc + t0 + 8) * Nn + i0 + il) * FOUT + o;
            *(float2*)p0 = make_float2(fmaxf(acc[mt][nt][0], 0.f), fmaxf(acc[mt][nt][1], 0.f));
            *(float2*)p1 = make_float2(fmaxf(acc[mt][nt][2], 0.f), fmaxf(acc[mt][nt][3], 0.f));
        }
    }
}

// ---------------------------------------------------------------------------
extern "C" void kernel_launch(void* const* d_in, const int* in_sizes, int n_in,
                              void* d_out, int out_size) {
    const float* x     = (const float*)d_in[0];
    const float* sa    = (const float*)d_in[1];
    const float* cheb  = (const float*)d_in[2];
    const float* Theta = (const float*)d_in[3];
    float* out = (float*)d_out;

    cudaFuncSetAttribute(k_gemm_mma, cudaFuncAttributeMaxDynamicSharedMemorySize, GEMM_SMEM);
    cudaFuncSetAttribute(k_proj_mma, cudaFuncAttributeMaxDynamicSharedMemorySize, PROJ_SMEM);

    // 0) att = fp16(cheb * sa); ThT = fp16(Theta^T)
    k_prep_att<<<24 * (NN / 4) / 256, 256>>>(cheb, sa);
    k_prep_tht<<<24, 256>>>(Theta);
    // 1) transpose + fp16 pack of x
    k_prep_x<<<1024, 256>>>(x);
    // 2) 24 GEMMs on tensor cores (1-term fp16, 2 CTAs/SM)
    dim3 grid(4, 8, Bc * Kc);
    k_gemm_mma<<<grid, 256, GEMM_SMEM>>>(0);
    // 3) tensor-core projection + relu
    dim3 pgrid(64, Bc);
    k_proj_mma<<<pgrid, 256, PROJ_SMEM>>>(out);
}